// round 6
// baseline (speedup 1.0000x reference)
#include <cuda_runtime.h>
#include <stdint.h>

// ============================ problem constants ============================
#define BATCH 8192
#define DIMK  2048
#define UNITS 2048
#define KW    (DIMK / 32)        // 64 packed 32-bit words along K

#define BM 128
#define BN 128
#define NT 512                   // 16 warps; per-thread tile 4x8

// Packed sign bits (bit = 1 iff value >= 0)
__device__ uint32_t g_xbits[(size_t)BATCH * KW];   // [row][w]   2 MB
__device__ uint32_t g_kbits[(size_t)UNITS * KW];   // [unit][w]  0.5 MB

// ---------------------------------------------------------------------------
// pack_x: each warp packs 256 consecutive floats -> 8 words.
// 8 coalesced 128B loads (MLP=8), 8 ballots, ONE 8-lane store.
// ---------------------------------------------------------------------------
__global__ void pack_x_kernel(const float* __restrict__ x) {
    const int warp = blockIdx.x * (blockDim.x >> 5) + (threadIdx.x >> 5);
    const int lane = threadIdx.x & 31;
    const float* p = x + (size_t)warp * 256;
    uint32_t mine = 0;
#pragma unroll
    for (int k = 0; k < 8; ++k) {
        float v = p[k * 32 + lane];
        unsigned m = __ballot_sync(0xffffffffu, v >= 0.0f);
        if (lane == k) mine = m;
    }
    if (lane < 8) g_xbits[(size_t)warp * 8 + lane] = mine;
}

// ---------------------------------------------------------------------------
// pack_k: kernel [DIMK, UNITS] f32 -> per-unit bit columns g_kbits[n*KW + w],
// bit j of word w = sign(kernel[(w*32+j)*UNITS + n]). Coalesced across n.
// ---------------------------------------------------------------------------
__global__ void pack_k_kernel(const float* __restrict__ k) {
    const int w = blockIdx.x;
    const int n = blockIdx.y * blockDim.x + threadIdx.x;
    const float* col = k + (size_t)w * 32 * UNITS + n;
    uint32_t bits = 0;
#pragma unroll
    for (int j = 0; j < 32; ++j) {
        bits |= (col[(size_t)j * UNITS] >= 0.0f ? 1u : 0u) << j;
    }
    g_kbits[(size_t)n * KW + w] = bits;
}

// ---------------------------------------------------------------------------
// Binary GEMM: out[r][c] = DIM - 2*popc(xrow ^ kcol) + bias[c]
//
// BM=BN=128, 512 threads, 4x8 outputs per thread:
//   rows tm + 32*i (tm = tid>>4, i<4), cols tn + 16*j (tn = tid&15, j<8).
//
// Shared tiles word-major with XOR swizzle on low 5 bits of the row index:
// element (w, r) at [w*128 + (r ^ (w & 31))].
//  - Loader: lanes = 32 consecutive w at fixed r -> 32 distinct banks.
//  - Compute A: 2 addresses/warp -> broadcast.
//  - Compute B: 16 distinct banks, 2-way broadcast each -> conflict-free.
//
// K unrolled by 2: acc += popc(p0) + popc(p1) -> IADD3/IMAD (ptxas balances
// the accumulate chain across alu/fma pipes).
// ---------------------------------------------------------------------------
extern __shared__ uint32_t smw[];   // sa[64*128] then sb[64*128] = 64 KB

__global__ void __launch_bounds__(NT)
bgemm_kernel(const float* __restrict__ bias, float* __restrict__ out) {
    uint32_t* sa = smw;
    uint32_t* sb = smw + KW * BM;

    const int tid  = threadIdx.x;
    const int row0 = blockIdx.y * BM;
    const int col0 = blockIdx.x * BN;

    // Cooperative load of both 64x128-word tiles (whole K dimension).
    {
        const int w  = tid & 63;
        const int r0 = tid >> 6;          // 0..7
        const int s  = w & 31;
        const uint32_t* ga = g_xbits + (size_t)row0 * KW + w;
        const uint32_t* gb = g_kbits + (size_t)col0 * KW + w;
#pragma unroll
        for (int it = 0; it < 16; ++it) {
            const int r = r0 + it * 8;
            sa[w * BM + (r ^ s)] = ga[(size_t)r * KW];
            sb[w * BN + (r ^ s)] = gb[(size_t)r * KW];
        }
    }
    __syncthreads();

    const int tm = tid >> 4;   // 0..31
    const int tn = tid & 15;   // 0..15

    int acc[4][8];
#pragma unroll
    for (int i = 0; i < 4; ++i)
#pragma unroll
        for (int j = 0; j < 8; ++j) acc[i][j] = 0;

#pragma unroll 2
    for (int w = 0; w < KW; w += 2) {
        const int s0 = w & 31;
        const int s1 = (w + 1) & 31;
        uint32_t a0[4], a1[4], b0[8], b1[8];
#pragma unroll
        for (int i = 0; i < 4; ++i) {
            a0[i] = sa[w * BM + ((tm + 32 * i) ^ s0)];
            a1[i] = sa[(w + 1) * BM + ((tm + 32 * i) ^ s1)];
        }
#pragma unroll
        for (int j = 0; j < 8; ++j) {
            b0[j] = sb[w * BN + ((tn + 16 * j) ^ s0)];
            b1[j] = sb[(w + 1) * BN + ((tn + 16 * j) ^ s1)];
        }
#pragma unroll
        for (int i = 0; i < 4; ++i)
#pragma unroll
            for (int j = 0; j < 8; ++j)
                acc[i][j] += __popc(a0[i] ^ b0[j]) + __popc(a1[i] ^ b1[j]);
    }

    // Epilogue: out = DIM - 2*acc + bias.
    float bv[8];
#pragma unroll
    for (int j = 0; j < 8; ++j) bv[j] = bias[col0 + tn + 16 * j];

#pragma unroll
    for (int i = 0; i < 4; ++i) {
        float* orow = out + (size_t)(row0 + tm + 32 * i) * UNITS + col0;
#pragma unroll
        for (int j = 0; j < 8; ++j) {
            orow[tn + 16 * j] = (float)(DIMK - 2 * acc[i][j]) + bv[j];
        }
    }
}

// ============================ harness entry ============================
extern "C" void kernel_launch(void* const* d_in, const int* in_sizes, int n_in,
                              void* d_out, int out_size) {
    (void)in_sizes; (void)n_in; (void)out_size;
    const float* x    = (const float*)d_in[0];
    const float* k    = (const float*)d_in[1];
    const float* bias = (const float*)d_in[2];
    float* out        = (float*)d_out;

    const int SMEM_BYTES = 2 * KW * BM * 4;          // 65536
    cudaFuncSetAttribute(bgemm_kernel, cudaFuncAttributeMaxDynamicSharedMemorySize,
                         SMEM_BYTES);

    pack_x_kernel<<<(BATCH * DIMK) / (256 * 8), 256>>>(x);
    pack_k_kernel<<<dim3(KW, UNITS / 256), 256>>>(k);
    bgemm_kernel<<<dim3(UNITS / BN, BATCH / BM), NT, SMEM_BYTES>>>(bias, out);
}

// round 7
// speedup vs baseline: 1.5391x; 1.5391x over previous
#include <cuda_runtime.h>
#include <stdint.h>

// ============================ problem constants ============================
#define BATCH 8192
#define DIMK  2048
#define UNITS 2048
#define KW    (DIMK / 32)        // 64 packed 32-bit words along K

#define BM 128
#define BN 128
#define NT 512                   // 16 warps; per-thread output tile 4x8
#define SROW 66                  // smem row stride in words (conflict-free LDS.64)

// Packed sign bits (bit = 1 iff value >= 0)
__device__ uint32_t g_xbits[(size_t)BATCH * KW];   // [row][w]   2 MB
__device__ uint32_t g_kbits[(size_t)UNITS * KW];   // [unit][w]  0.5 MB

#define LOP3_(r, a, b, c, lut) \
    asm("lop3.b32 %0, %1, %2, %3, " #lut ";" : "=r"(r) : "r"(a), "r"(b), "r"(c))

// ---------------------------------------------------------------------------
// pack_x: each warp packs 256 consecutive floats -> 8 words (ballot order).
// ---------------------------------------------------------------------------
__global__ void pack_x_kernel(const float* __restrict__ x) {
    const int warp = blockIdx.x * (blockDim.x >> 5) + (threadIdx.x >> 5);
    const int lane = threadIdx.x & 31;
    const float* p = x + (size_t)warp * 256;
    uint32_t mine = 0;
#pragma unroll
    for (int k = 0; k < 8; ++k) {
        float v = p[k * 32 + lane];
        unsigned m = __ballot_sync(0xffffffffu, v >= 0.0f);
        if (lane == k) mine = m;
    }
    if (lane < 8) g_xbits[(size_t)warp * 8 + lane] = mine;
}

// ---------------------------------------------------------------------------
// pack_k: kernel [DIMK, UNITS] f32 -> per-unit bit columns g_kbits[n*KW + w].
// ---------------------------------------------------------------------------
__global__ void pack_k_kernel(const float* __restrict__ k) {
    const int w = blockIdx.x;
    const int n = blockIdx.y * blockDim.x + threadIdx.x;
    const float* col = k + (size_t)w * 32 * UNITS + n;
    uint32_t bits = 0;
#pragma unroll
    for (int j = 0; j < 32; ++j) {
        bits |= (col[(size_t)j * UNITS] >= 0.0f ? 1u : 0u) << j;
    }
    g_kbits[(size_t)n * KW + w] = bits;
}

// ---------------------------------------------------------------------------
// Binary GEMM with CSA popcount compression.
// out[r][c] = DIM - 2 * sum_w popc(x[r][w] ^ k[c][w]) + bias[c]
//
// Per output, per group of 8 K-words: 8 XOR, 8 LOP3 (full-adder tree),
// 4 POPC (weights 1,1,2,4), 3 adds. POPC count halved vs naive; the tree
// runs on the (previously idle) alu pipe.
//
// Smem: row-major tiles, stride 66 words. LDS.64 banks: word = 66*r + w;
// 66 mod 32 = 2 -> 16 distinct row-offsets cover all 32 banks once,
// duplicated rows broadcast. Conflict-free, immediate-offset addressing.
// ---------------------------------------------------------------------------
extern __shared__ uint32_t smw[];   // sa[128*66] then sb[128*66] = 67584 B

__global__ void __launch_bounds__(NT)
bgemm_kernel(const float* __restrict__ bias, float* __restrict__ out) {
    uint32_t* sa = smw;
    uint32_t* sb = smw + BM * SROW;

    const int tid  = threadIdx.x;
    const int row0 = blockIdx.y * BM;
    const int col0 = blockIdx.x * BN;

    // Cooperative load: whole-K tiles, uint2 global reads, STS.64 stores.
    // Lanes: consecutive wp at fixed r -> global 256B contiguous; smem banks
    // 2*wp..2*wp+1 cover all 32 banks -> conflict-free.
#pragma unroll
    for (int it = 0; it < (BM * (KW / 2)) / NT; ++it) {
        const int idx = tid + it * NT;
        const int r = idx >> 5;
        const int wp = idx & 31;
        uint2 va = ((const uint2*)g_xbits)[(size_t)(row0 + r) * (KW / 2) + wp];
        *(uint2*)(sa + r * SROW + 2 * wp) = va;
        uint2 vb = ((const uint2*)g_kbits)[(size_t)(col0 + r) * (KW / 2) + wp];
        *(uint2*)(sb + r * SROW + 2 * wp) = vb;
    }
    __syncthreads();

    const int tm = tid >> 4;   // 0..31, rows tm + 32*i
    const int tn = tid & 15;   // 0..15, cols tn + 16*j

    int acc[4][8];
#pragma unroll
    for (int i = 0; i < 4; ++i)
#pragma unroll
        for (int j = 0; j < 8; ++j) acc[i][j] = 0;

#pragma unroll 1
    for (int g = 0; g < KW / 8; ++g) {
        const int wb = g * 8;

        uint32_t A[4][8];
#pragma unroll
        for (int i = 0; i < 4; ++i) {
            const uint32_t* pa = sa + (tm + 32 * i) * SROW + wb;
#pragma unroll
            for (int k = 0; k < 4; ++k) {
                uint2 v = *(const uint2*)(pa + 2 * k);
                A[i][2 * k] = v.x;
                A[i][2 * k + 1] = v.y;
            }
        }

#pragma unroll
        for (int j = 0; j < 8; ++j) {
            uint32_t B[8];
            const uint32_t* pb = sb + (tn + 16 * j) * SROW + wb;
#pragma unroll
            for (int k = 0; k < 4; ++k) {
                uint2 v = *(const uint2*)(pb + 2 * k);
                B[2 * k] = v.x;
                B[2 * k + 1] = v.y;
            }
#pragma unroll
            for (int i = 0; i < 4; ++i) {
                uint32_t x0 = A[i][0] ^ B[0], x1 = A[i][1] ^ B[1];
                uint32_t x2 = A[i][2] ^ B[2], x3 = A[i][3] ^ B[3];
                uint32_t x4 = A[i][4] ^ B[4], x5 = A[i][5] ^ B[5];
                uint32_t x6 = A[i][6] ^ B[6], x7 = A[i][7] ^ B[7];
                uint32_t s1, c1, s2, c2, s3, c3, s4, c4;
                LOP3_(s1, x0, x1, x2, 0x96);   // xor3
                LOP3_(c1, x0, x1, x2, 0xE8);   // maj
                LOP3_(s2, x3, x4, x5, 0x96);
                LOP3_(c2, x3, x4, x5, 0xE8);
                LOP3_(s3, s1, s2, x6, 0x96);
                LOP3_(c3, s1, s2, x6, 0xE8);
                LOP3_(s4, c1, c2, c3, 0x96);   // weight-2 plane
                LOP3_(c4, c1, c2, c3, 0xE8);   // weight-4 plane
                // sum = popc(s3) + popc(x7) + 2*popc(s4) + 4*popc(c4)
                acc[i][j] += __popc(s3) + __popc(x7);
                int t = __popc(s4) + (__popc(c4) << 1);
                acc[i][j] += t << 1;
            }
        }
    }

    // Epilogue: out = DIM - 2*acc + bias. Each warp store instr covers
    // 2 rows x 16 consecutive cols (two full 64B sectors).
    float bv[8];
#pragma unroll
    for (int j = 0; j < 8; ++j) bv[j] = bias[col0 + tn + 16 * j];

#pragma unroll
    for (int i = 0; i < 4; ++i) {
        float* orow = out + (size_t)(row0 + tm + 32 * i) * UNITS + col0;
#pragma unroll
        for (int j = 0; j < 8; ++j) {
            orow[tn + 16 * j] = (float)(DIMK - 2 * acc[i][j]) + bv[j];
        }
    }
}

// ============================ harness entry ============================
extern "C" void kernel_launch(void* const* d_in, const int* in_sizes, int n_in,
                              void* d_out, int out_size) {
    (void)in_sizes; (void)n_in; (void)out_size;
    const float* x    = (const float*)d_in[0];
    const float* k    = (const float*)d_in[1];
    const float* bias = (const float*)d_in[2];
    float* out        = (float*)d_out;

    const int SMEM_BYTES = 2 * BM * SROW * 4;        // 67584
    cudaFuncSetAttribute(bgemm_kernel, cudaFuncAttributeMaxDynamicSharedMemorySize,
                         SMEM_BYTES);

    pack_x_kernel<<<(BATCH * DIMK) / (256 * 8), 256>>>(x);
    pack_k_kernel<<<dim3(KW, UNITS / 256), 256>>>(k);
    bgemm_kernel<<<dim3(UNITS / BN, BATCH / BM), NT, SMEM_BYTES>>>(bias, out);
}